// round 1
// baseline (speedup 1.0000x reference)
#include <cuda_runtime.h>

#define N_NODES 262144
#define N_EDGES 1048576
#define N_GRAPHS 8192
#define H 128
#define H2 256
#define LAYERS 4
#define FA 9
#define VA 64
#define FB 3
#define VB 8

// ---------------- scratch (device globals; no allocations allowed) ----------
__device__ float g_h[(size_t)N_NODES * H];        // node features   [N,128]
__device__ float g_agg[(size_t)N_NODES * H];      // message agg     [N,128]
__device__ float g_t[(size_t)N_NODES * H2];       // wide activations[N,256]
__device__ float g_vn[(size_t)N_GRAPHS * H];      // virtual node    [G,128]
__device__ float g_pooled[(size_t)N_GRAPHS * H2]; // pooled          [G,256]

// ---------------- atom encoder: h[n] = sum_f atom_emb[f, x[n,f], :] ---------
__global__ void atom_kernel(const int* __restrict__ x,
                            const float* __restrict__ emb,
                            float* __restrict__ h) {
    int idx = blockIdx.x * blockDim.x + threadIdx.x;
    int n = idx >> 5;
    int c = (idx & 31) << 2;
    float4 acc = make_float4(0.f, 0.f, 0.f, 0.f);
#pragma unroll
    for (int f = 0; f < FA; f++) {
        int v = x[n * FA + f];
        float4 e = *(const float4*)(emb + ((size_t)(f * VA + v) * H) + c);
        acc.x += e.x; acc.y += e.y; acc.z += e.z; acc.w += e.w;
    }
    *(float4*)(h + (size_t)n * H + c) = acc;
}

// ---------------- vn init: broadcast vn_emb to all graphs -------------------
__global__ void vninit_kernel(const float* __restrict__ vn_emb,
                              float* __restrict__ vn) {
    int idx = blockIdx.x * blockDim.x + threadIdx.x;
    int g = idx >> 5;
    int c = (idx & 31) << 2;
    *(float4*)(vn + (size_t)g * H + c) = *(const float4*)(vn_emb + c);
}

// ---------------- h += vn[batch]; also zero agg for the edge pass ----------
__global__ void addvn_kernel(float* __restrict__ h,
                             const float* __restrict__ vn,
                             const int* __restrict__ batch,
                             float* __restrict__ agg) {
    int idx = blockIdx.x * blockDim.x + threadIdx.x;
    int n = idx >> 5;
    int c = (idx & 31) << 2;
    int g = batch[n];
    float4 hv = *(float4*)(h + (size_t)n * H + c);
    float4 vv = *(const float4*)(vn + (size_t)g * H + c);
    hv.x += vv.x; hv.y += vv.y; hv.z += vv.z; hv.w += vv.w;
    *(float4*)(h + (size_t)n * H + c) = hv;
    *(float4*)(agg + (size_t)n * H + c) = make_float4(0.f, 0.f, 0.f, 0.f);
}

// ---------------- edge message: agg[dst] += relu(h[src] + bond_emb(e)) ------
__global__ void edge_kernel(const int* __restrict__ ei,
                            const int* __restrict__ ea,
                            const float* __restrict__ bond, // [FB,VB,H] slice
                            const float* __restrict__ h,
                            float* __restrict__ agg) {
    __shared__ float tab[FB * VB * H]; // 12 KB
    for (int i = threadIdx.x; i < FB * VB * H; i += blockDim.x) tab[i] = bond[i];
    __syncthreads();
    int e = (blockIdx.x * blockDim.x + threadIdx.x) >> 5; // one warp per edge
    int lane = threadIdx.x & 31;
    int src = ei[e];
    int dst = ei[N_EDGES + e];
    int a0 = ea[e * 3 + 0], a1 = ea[e * 3 + 1], a2 = ea[e * 3 + 2];
    int c = lane << 2;
    float4 hv = *(const float4*)(h + (size_t)src * H + c);
    float4 e0 = *(const float4*)(tab + (0 * VB + a0) * H + c);
    float4 e1 = *(const float4*)(tab + (1 * VB + a1) * H + c);
    float4 e2 = *(const float4*)(tab + (2 * VB + a2) * H + c);
    float m0 = fmaxf(hv.x + e0.x + e1.x + e2.x, 0.f);
    float m1 = fmaxf(hv.y + e0.y + e1.y + e2.y, 0.f);
    float m2 = fmaxf(hv.z + e0.z + e1.z + e2.z, 0.f);
    float m3 = fmaxf(hv.w + e0.w + e1.w + e2.w, 0.f);
    float* p = agg + (size_t)dst * H + c;
    atomicAdd(p + 0, m0);
    atomicAdd(p + 1, m1);
    atomicAdd(p + 2, m2);
    atomicAdd(p + 3, m3);
}

// ---------------- fused tiled GEMM ------------------------------------------
// MODE_A: 0 = plain A[M,K]
//         1 = A := (1+eps)*h + agg     (h=A, agg=A2, both [M,128] when K=128)
//         2 = A := concat(vn[batch], h) (h=A [M,128], vn=A2 [G,128], K=256)
// BN_RELU: epilogue y = relu((x+bias-m)*g*rsqrt(v+eps)+b) else y = x+bias
template <int MODE_A, bool BN_RELU>
__global__ __launch_bounds__(256) void gemm_fused(
    const float* __restrict__ A, const float* __restrict__ A2,
    const int* __restrict__ batch,
    const float* __restrict__ W, const float* __restrict__ bias,
    const float* __restrict__ bng, const float* __restrict__ bnb,
    const float* __restrict__ bnm, const float* __restrict__ bnv,
    float* __restrict__ C, int M, int K, int Ncol,
    const float* __restrict__ epsp) {
    __shared__ float As[16][64];
    __shared__ float Bs[16][64];
    const int tid = threadIdx.x;
    const int m0 = blockIdx.x * 64;
    const int n0 = blockIdx.y * 64;
    const int tr = tid >> 4;         // 0..15  (4 rows each)
    const int tc = tid & 15;         // 0..15  (4 cols each)
    const int am = tid & 63;         // A tile row this thread loads
    const int ak = (tid >> 6) << 2;  // A tile k (4 at a time)
    const int bn = (tid & 15) << 2;  // B tile col
    const int bk = tid >> 4;         // B tile row
    const int grow = m0 + am;
    float c0 = 1.0f;
    if (MODE_A == 1) c0 = 1.0f + __ldg(epsp);
    int bg = 0;
    if (MODE_A == 2) bg = batch[grow];

    float acc[4][4];
#pragma unroll
    for (int i = 0; i < 4; i++)
#pragma unroll
        for (int j = 0; j < 4; j++) acc[i][j] = 0.f;

    for (int k0 = 0; k0 < K; k0 += 16) {
        float4 a4;
        int gk = k0 + ak;
        if (MODE_A == 0) {
            a4 = *(const float4*)(A + (size_t)grow * K + gk);
        } else if (MODE_A == 1) {
            float4 hv = *(const float4*)(A + (size_t)grow * K + gk);
            float4 gv = *(const float4*)(A2 + (size_t)grow * K + gk);
            a4.x = fmaf(c0, hv.x, gv.x);
            a4.y = fmaf(c0, hv.y, gv.y);
            a4.z = fmaf(c0, hv.z, gv.z);
            a4.w = fmaf(c0, hv.w, gv.w);
        } else {
            if (gk < H) a4 = *(const float4*)(A2 + (size_t)bg * H + gk);
            else        a4 = *(const float4*)(A + (size_t)grow * H + (gk - H));
        }
        As[ak + 0][am] = a4.x;
        As[ak + 1][am] = a4.y;
        As[ak + 2][am] = a4.z;
        As[ak + 3][am] = a4.w;
        *(float4*)(&Bs[bk][bn]) =
            *(const float4*)(W + (size_t)(k0 + bk) * Ncol + n0 + bn);
        __syncthreads();
#pragma unroll
        for (int kk = 0; kk < 16; kk++) {
            float ar[4], br[4];
            *(float4*)ar = *(const float4*)(&As[kk][tr << 2]);
            *(float4*)br = *(const float4*)(&Bs[kk][tc << 2]);
#pragma unroll
            for (int i = 0; i < 4; i++)
#pragma unroll
                for (int j = 0; j < 4; j++)
                    acc[i][j] = fmaf(ar[i], br[j], acc[i][j]);
        }
        __syncthreads();
    }

    float sc[4], off[4];
#pragma unroll
    for (int j = 0; j < 4; j++) {
        int col = n0 + (tc << 2) + j;
        if (BN_RELU) {
            float s = __ldg(bng + col) * rsqrtf(__ldg(bnv + col) + 1e-5f);
            sc[j] = s;
            off[j] = (__ldg(bias + col) - __ldg(bnm + col)) * s + __ldg(bnb + col);
        } else {
            sc[j] = 1.0f;
            off[j] = __ldg(bias + col);
        }
    }
#pragma unroll
    for (int i = 0; i < 4; i++) {
        int row = m0 + (tr << 2) + i;
        float4 v;
        float* vp = (float*)&v;
#pragma unroll
        for (int j = 0; j < 4; j++) {
            float y = fmaf(acc[i][j], sc[j], off[j]);
            if (BN_RELU) y = fmaxf(y, 0.0f);
            vp[j] = y;
        }
        *(float4*)(C + (size_t)row * Ncol + n0 + (tc << 2)) = v;
    }
}

// ---------------- zero pooled buffer ----------------------------------------
__global__ void zero_pooled_kernel(float4* __restrict__ p) {
    int idx = blockIdx.x * blockDim.x + threadIdx.x; // exactly G*H2/4 threads
    p[idx] = make_float4(0.f, 0.f, 0.f, 0.f);
}

// ---------------- graph pooling: pooled[batch[n]] += t[n] -------------------
__global__ void pool_kernel(const float* __restrict__ t,
                            const int* __restrict__ batch,
                            float* __restrict__ pooled) {
    int idx = blockIdx.x * blockDim.x + threadIdx.x;
    int n = idx >> 6;
    int c = (idx & 63) << 2;
    int g = batch[n];
    float4 v = *(const float4*)(t + (size_t)n * H2 + c);
    float* p = pooled + (size_t)g * H2 + c;
    atomicAdd(p + 0, v.x);
    atomicAdd(p + 1, v.y);
    atomicAdd(p + 2, v.z);
    atomicAdd(p + 3, v.w);
}

// ---------------- final head: clip(relu(vn@pW1+pb1)@pW2+pb2, 0, 50) ---------
__global__ void final_kernel(const float* __restrict__ vn,
                             const float* __restrict__ pW1,
                             const float* __restrict__ pb1,
                             const float* __restrict__ pW2,
                             const float* __restrict__ pb2,
                             float* __restrict__ out) {
    int g = blockIdx.x;
    int j = threadIdx.x; // 128
    __shared__ float vrow[H];
    vrow[j] = vn[(size_t)g * H + j];
    __syncthreads();
    float acc = pb1[j];
#pragma unroll 8
    for (int k = 0; k < H; k++) acc = fmaf(vrow[k], __ldg(pW1 + k * H + j), acc);
    float val = fmaxf(acc, 0.0f) * __ldg(pW2 + j);
#pragma unroll
    for (int o = 16; o > 0; o >>= 1) val += __shfl_down_sync(0xffffffffu, val, o);
    __shared__ float part[4];
    if ((j & 31) == 0) part[j >> 5] = val;
    __syncthreads();
    if (j == 0) {
        float s = part[0] + part[1] + part[2] + part[3] + pb2[0];
        out[g] = fminf(fmaxf(s, 0.0f), 50.0f);
    }
}

// ---------------- launch -----------------------------------------------------
extern "C" void kernel_launch(void* const* d_in, const int* in_sizes, int n_in,
                              void* d_out, int out_size) {
    const int* x          = (const int*)d_in[0];
    const int* edge_index = (const int*)d_in[1];
    const int* edge_attr  = (const int*)d_in[2];
    const int* batch      = (const int*)d_in[3];
    const float* atom_emb  = (const float*)d_in[4];
    const float* vn_emb    = (const float*)d_in[5];
    const float* bond_emb  = (const float*)d_in[6];
    const float* conv_eps  = (const float*)d_in[7];
    const float* conv_W1   = (const float*)d_in[8];
    const float* conv_b1   = (const float*)d_in[9];
    const float* conv_bn_g = (const float*)d_in[10];
    const float* conv_bn_b = (const float*)d_in[11];
    const float* conv_bn_m = (const float*)d_in[12];
    const float* conv_bn_v = (const float*)d_in[13];
    const float* conv_W2   = (const float*)d_in[14];
    const float* conv_b2   = (const float*)d_in[15];
    const float* vn1_W  = (const float*)d_in[16];
    const float* vn1_b  = (const float*)d_in[17];
    const float* vn1_g  = (const float*)d_in[18];
    const float* vn1_be = (const float*)d_in[19];
    const float* vn1_m  = (const float*)d_in[20];
    const float* vn1_v  = (const float*)d_in[21];
    const float* vn2_W  = (const float*)d_in[22];
    const float* vn2_b  = (const float*)d_in[23];
    const float* vn2_g  = (const float*)d_in[24];
    const float* vn2_be = (const float*)d_in[25];
    const float* vn2_m  = (const float*)d_in[26];
    const float* vn2_v  = (const float*)d_in[27];
    const float* pW1 = (const float*)d_in[28];
    const float* pb1 = (const float*)d_in[29];
    const float* pW2 = (const float*)d_in[30];
    const float* pb2 = (const float*)d_in[31];
    float* out = (float*)d_out;

    float *h, *agg, *t, *vn, *pooled;
    cudaGetSymbolAddress((void**)&h, g_h);
    cudaGetSymbolAddress((void**)&agg, g_agg);
    cudaGetSymbolAddress((void**)&t, g_t);
    cudaGetSymbolAddress((void**)&vn, g_vn);
    cudaGetSymbolAddress((void**)&pooled, g_pooled);

    atom_kernel<<<(N_NODES * 32) / 256, 256>>>(x, atom_emb, h);
    vninit_kernel<<<(N_GRAPHS * 32) / 256, 256>>>(vn_emb, vn);

    for (int i = 0; i < LAYERS; i++) {
        // h += vn[batch]; agg = 0
        addvn_kernel<<<(N_NODES * 32) / 256, 256>>>(h, vn, batch, agg);
        // agg[dst] += relu(h[src] + bond_emb)
        edge_kernel<<<N_EDGES / 8, 256>>>(edge_index, edge_attr,
                                          bond_emb + (size_t)i * FB * VB * H, h, agg);
        // t = relu(bn(((1+eps)h + agg) @ W1 + b1))   [N,256]
        gemm_fused<1, true><<<dim3(N_NODES / 64, H2 / 64), 256>>>(
            h, agg, nullptr, conv_W1 + (size_t)i * H * H2, conv_b1 + i * H2,
            conv_bn_g + i * H2, conv_bn_b + i * H2, conv_bn_m + i * H2,
            conv_bn_v + i * H2, t, N_NODES, H, H2, conv_eps + i);
        // h = t @ W2 + b2                              [N,128]
        gemm_fused<0, false><<<dim3(N_NODES / 64, H / 64), 256>>>(
            t, nullptr, nullptr, conv_W2 + (size_t)i * H2 * H, conv_b2 + i * H,
            nullptr, nullptr, nullptr, nullptr, h, N_NODES, H2, H, nullptr);
        // t = relu(bn(concat(vn[batch], h) @ vn1_W + vn1_b))  [N,256]
        gemm_fused<2, true><<<dim3(N_NODES / 64, H2 / 64), 256>>>(
            h, vn, batch, vn1_W + (size_t)i * H2 * H2, vn1_b + i * H2,
            vn1_g + i * H2, vn1_be + i * H2, vn1_m + i * H2, vn1_v + i * H2,
            t, N_NODES, H2, H2, nullptr);
        // pooled = segment_sum(t, batch)
        zero_pooled_kernel<<<(N_GRAPHS * H2 / 4) / 256, 256>>>((float4*)pooled);
        pool_kernel<<<(N_NODES * 64) / 256, 256>>>(t, batch, pooled);
        // vn = relu(bn(pooled @ vn2_W + vn2_b))        [G,128]
        gemm_fused<0, true><<<dim3(N_GRAPHS / 64, H / 64), 256>>>(
            pooled, nullptr, nullptr, vn2_W + (size_t)i * H2 * H, vn2_b + i * H,
            vn2_g + i * H, vn2_be + i * H, vn2_m + i * H, vn2_v + i * H,
            vn, N_GRAPHS, H2, H, nullptr);
    }
    final_kernel<<<N_GRAPHS, 128>>>(vn, pW1, pb1, pW2, pb2, out);
}